// round 1
// baseline (speedup 1.0000x reference)
#include <cuda_runtime.h>

// Problem constants
#define Bn 32
#define Cn 64
#define Hn 112
#define Wn 112
static constexpr int HW    = Hn * Wn;        // 12544
static constexpr int BHW   = Bn * HW;        // 401408
static constexpr int TOTAL = Bn * Cn * HW;   // 25690112
static constexpr float ALPHA = 0.25f;

// Scratch (no cudaMalloc allowed): bit-planes + intermediate activation
__device__ unsigned long long g_bits1[BHW];
__device__ unsigned long long g_bits2[BHW];
__device__ float g_out1[TOTAL];                       // ~103 MB .bss
__device__ unsigned long long g_w[2][Cn][9];          // packed sign words
__device__ float g_scale[2][Cn];                      // per-oc mean(|w|)

// ---------------------------------------------------------------------------
// K0: weight prep — per-oc scale = mean|w| over (ic,kh,kw); pack sign bits.
// dsign: w >= 0 -> +1 (bit=1), else -1 (bit=0). OIHW layout, tap = kh*3+kw.
// ---------------------------------------------------------------------------
__global__ void prep_weights(const float* __restrict__ w3,
                             const float* __restrict__ wpw)
{
    int t = threadIdx.x;            // 0..127
    int set = t >> 6;               // 0 = w3, 1 = w_pw
    int oc  = t & 63;
    const float* w = set ? wpw : w3;
    float s = 0.f;
    #pragma unroll
    for (int tap = 0; tap < 9; tap++) {
        unsigned long long word = 0ull;
        for (int ic = 0; ic < 64; ic++) {
            float v = w[(oc * 64 + ic) * 9 + tap];
            s += fabsf(v);
            word |= (unsigned long long)(v >= 0.f) << ic;
        }
        g_w[set][oc][tap] = word;
    }
    g_scale[set][oc] = s * (1.f / 576.f);
}

// ---------------------------------------------------------------------------
// K1: pack1 — bits1[pix] = bitpack over c of (x*BETA1 + b11[c] >= 0), BETA1=1.
// Thread-per-pixel; the c-loop is coalesced across the warp (lane-consecutive
// pixels at each channel plane).
// ---------------------------------------------------------------------------
__global__ void pack1_kernel(const float* __restrict__ x,
                             const float* __restrict__ b11)
{
    __shared__ float sb[64];
    if (threadIdx.x < 64) sb[threadIdx.x] = b11[threadIdx.x];
    __syncthreads();

    int pix = blockIdx.x * blockDim.x + threadIdx.x;
    if (pix >= BHW) return;
    int b = pix / HW, hw = pix - b * HW;
    const float* xp = x + (size_t)b * Cn * HW + hw;

    unsigned long long word = 0ull;
    #pragma unroll 8
    for (int c = 0; c < 64; c++)
        word |= (unsigned long long)(xp[c * HW] + sb[c] >= 0.f) << c;
    g_bits1[pix] = word;
}

// ---------------------------------------------------------------------------
// Binary conv + fused epilogue.
//   conv(b,oc,y,x) = scale_oc * (64*n_valid - 2 * sum_taps popc((nb^w)&mask))
//   o = prelu(resid + ALPHA*conv + bA, aP) + bB
// STAGE==1 additionally packs bits2 (o + bPack >= 0) in-register.
// Zero-padding handled branchlessly: (nb^w)&mask fuses to one LOP3 per half.
// ---------------------------------------------------------------------------
template <int STAGE>
__device__ __forceinline__ void conv_body(const float* __restrict__ resid,
                                          float* __restrict__ outp,
                                          const float* __restrict__ bA,
                                          const float* __restrict__ aP,
                                          const float* __restrict__ bB,
                                          const float* __restrict__ bPack)
{
    __shared__ unsigned long long sw[Cn * 9];
    __shared__ float ss[64], sA[64], sP[64], sB[64], sK[64];

    const unsigned long long* gw = &g_w[STAGE - 1][0][0];
    for (int i = threadIdx.x; i < Cn * 9; i += blockDim.x) sw[i] = gw[i];
    if (threadIdx.x < 64) {
        ss[threadIdx.x] = g_scale[STAGE - 1][threadIdx.x];
        sA[threadIdx.x] = bA[threadIdx.x];
        sP[threadIdx.x] = aP[threadIdx.x];
        sB[threadIdx.x] = bB[threadIdx.x];
        sK[threadIdx.x] = (STAGE == 1) ? bPack[threadIdx.x] : 0.f;
    }
    __syncthreads();

    int pix = blockIdx.x * blockDim.x + threadIdx.x;
    if (pix >= BHW) return;
    int b = pix / HW, hw = pix - b * HW;
    int y = hw / Wn, xx = hw - y * Wn;

    const unsigned long long* bp =
        ((STAGE == 1) ? g_bits1 : g_bits2) + (size_t)b * HW;

    unsigned long long nb[9], mk[9];
    int nv = 0;
    #pragma unroll
    for (int dy = -1; dy <= 1; dy++)
        #pragma unroll
        for (int dx = -1; dx <= 1; dx++) {
            int t  = (dy + 1) * 3 + (dx + 1);
            int yy = y + dy, xc = xx + dx;
            bool ok = ((unsigned)yy < (unsigned)Hn) & ((unsigned)xc < (unsigned)Wn);
            nv += ok;
            mk[t] = ok ? ~0ull : 0ull;
            nb[t] = ok ? bp[yy * Wn + xc] : 0ull;
        }
    float basef = 64.f * (float)nv;

    const float* rp = resid + (size_t)b * Cn * HW + hw;
    float*       op = outp  + (size_t)b * Cn * HW + hw;

    unsigned long long pk = 0ull;
    #pragma unroll 4
    for (int oc = 0; oc < 64; oc++) {
        const unsigned long long* wr = sw + oc * 9;
        int acc = 0;
        #pragma unroll
        for (int t = 0; t < 9; t++)
            acc += __popcll((nb[t] ^ wr[t]) & mk[t]);
        float conv = ss[oc] * fmaf(-2.f, (float)acc, basef);
        float o  = fmaf(ALPHA, conv, rp[oc * HW]);
        float tm = o + sA[oc];
        o = (tm >= 0.f ? tm : sP[oc] * tm) + sB[oc];
        op[oc * HW] = o;
        if (STAGE == 1)
            pk |= (unsigned long long)(o + sK[oc] >= 0.f) << oc;
    }
    if (STAGE == 1) g_bits2[pix] = pk;
}

__global__ void conv1_kernel(const float* __restrict__ x,
                             const float* __restrict__ b12,
                             const float* __restrict__ a1,
                             const float* __restrict__ b13,
                             const float* __restrict__ b21)
{
    conv_body<1>(x, g_out1, b12, a1, b13, b21);
}

__global__ void conv2_kernel(float* __restrict__ out,
                             const float* __restrict__ b22,
                             const float* __restrict__ a2,
                             const float* __restrict__ b23)
{
    conv_body<2>(g_out1, out, b22, a2, b23, nullptr);
}

// ---------------------------------------------------------------------------
extern "C" void kernel_launch(void* const* d_in, const int* in_sizes, int n_in,
                              void* d_out, int out_size)
{
    const float* x   = (const float*)d_in[0];
    const float* w3  = (const float*)d_in[1];
    const float* wpw = (const float*)d_in[2];
    const float* b11 = (const float*)d_in[3];
    const float* b12 = (const float*)d_in[4];
    const float* b13 = (const float*)d_in[5];
    const float* b21 = (const float*)d_in[6];
    const float* b22 = (const float*)d_in[7];
    const float* b23 = (const float*)d_in[8];
    const float* a1  = (const float*)d_in[9];
    const float* a2  = (const float*)d_in[10];
    float* out = (float*)d_out;

    int blocks = (BHW + 255) / 256;
    prep_weights<<<1, 128>>>(w3, wpw);
    pack1_kernel<<<blocks, 256>>>(x, b11);
    conv1_kernel<<<blocks, 256>>>(x, b12, a1, b13, b21);
    conv2_kernel<<<blocks, 256>>>(out, b22, a2, b23);
}

// round 3
// speedup vs baseline: 1.0548x; 1.0548x over previous
#include <cuda_runtime.h>

// Problem constants
#define Bn 32
#define Cn 64
#define Hn 112
#define Wn 112
static constexpr int HW    = Hn * Wn;        // 12544
static constexpr int BHW   = Bn * HW;        // 401408
static constexpr int TOTAL = Bn * Cn * HW;   // 25690112
static constexpr float ALPHA = 0.25f;

// Scratch (no cudaMalloc allowed): bit-planes + intermediate activation
__device__ unsigned long long g_bits1[BHW];
__device__ unsigned long long g_bits2[BHW];
__device__ float g_out1[TOTAL];                       // ~103 MB .bss
__device__ unsigned long long g_w[2][Cn][9];          // packed sign words
__device__ float g_scale[2][Cn];                      // per-oc mean(|w|)

// ---------------------------------------------------------------------------
// K0: weight prep — per-oc scale = mean|w| over (ic,kh,kw); pack sign bits.
// dsign: w >= 0 -> +1 (bit=1), else -1 (bit=0). OIHW layout, tap = kh*3+kw.
// ---------------------------------------------------------------------------
__global__ void prep_weights(const float* __restrict__ w3,
                             const float* __restrict__ wpw)
{
    int t = threadIdx.x;            // 0..127
    int set = t >> 6;               // 0 = w3, 1 = w_pw
    int oc  = t & 63;
    const float* w = set ? wpw : w3;
    float s = 0.f;
    #pragma unroll
    for (int tap = 0; tap < 9; tap++) {
        unsigned long long word = 0ull;
        for (int ic = 0; ic < 64; ic++) {
            float v = w[(oc * 64 + ic) * 9 + tap];
            s += fabsf(v);
            word |= (unsigned long long)(v >= 0.f) << ic;
        }
        g_w[set][oc][tap] = word;
    }
    g_scale[set][oc] = s * (1.f / 576.f);
}

// ---------------------------------------------------------------------------
// K1: pack1 — bits1[pix] = bitpack over c of (x + b11[c] >= 0), BETA1=1.
// ---------------------------------------------------------------------------
__global__ void pack1_kernel(const float* __restrict__ x,
                             const float* __restrict__ b11)
{
    __shared__ float sb[64];
    if (threadIdx.x < 64) sb[threadIdx.x] = b11[threadIdx.x];
    __syncthreads();

    int pix = blockIdx.x * blockDim.x + threadIdx.x;
    if (pix >= BHW) return;
    int b = pix / HW, hw = pix - b * HW;
    const float* xp = x + (size_t)b * Cn * HW + hw;

    unsigned long long word = 0ull;
    #pragma unroll 8
    for (int c = 0; c < 64; c++)
        word |= (unsigned long long)(xp[c * HW] + sb[c] >= 0.f) << c;
    g_bits1[pix] = word;
}

// ---------------------------------------------------------------------------
// Binary conv + fused epilogue, restructured for latency hiding:
// oc processed in chunks of 8 with three phases per chunk:
//   (1) batch 8 independent residual LDGs            (MLP = 8)
//   (2) pure-ALU popcount phase for 8 oc             (~720 cyc, hides DRAM lat)
//   (3) float epilogue + coalesced stores
// ---------------------------------------------------------------------------
template <int STAGE>
__device__ __forceinline__ void conv_body(const float* __restrict__ resid,
                                          float* __restrict__ outp,
                                          const float* __restrict__ bA,
                                          const float* __restrict__ aP,
                                          const float* __restrict__ bB,
                                          const float* __restrict__ bPack)
{
    __shared__ unsigned long long sw[Cn * 9];
    __shared__ float ss[64], sA[64], sP[64], sB[64], sK[64];

    const unsigned long long* gw = &g_w[STAGE - 1][0][0];
    for (int i = threadIdx.x; i < Cn * 9; i += blockDim.x) sw[i] = gw[i];
    if (threadIdx.x < 64) {
        ss[threadIdx.x] = g_scale[STAGE - 1][threadIdx.x];
        sA[threadIdx.x] = bA[threadIdx.x];
        sP[threadIdx.x] = aP[threadIdx.x];
        sB[threadIdx.x] = bB[threadIdx.x];
        sK[threadIdx.x] = (STAGE == 1) ? bPack[threadIdx.x] : 0.f;
    }
    __syncthreads();

    int pix = blockIdx.x * blockDim.x + threadIdx.x;
    if (pix >= BHW) return;
    int b = pix / HW, hw = pix - b * HW;
    int y = hw / Wn, xx = hw - y * Wn;

    const unsigned long long* bp =
        ((STAGE == 1) ? g_bits1 : g_bits2) + (size_t)b * HW;

    unsigned long long nb[9], mk[9];
    int nv = 0;
    #pragma unroll
    for (int dy = -1; dy <= 1; dy++)
        #pragma unroll
        for (int dx = -1; dx <= 1; dx++) {
            int t  = (dy + 1) * 3 + (dx + 1);
            int yy = y + dy, xc = xx + dx;
            bool ok = ((unsigned)yy < (unsigned)Hn) & ((unsigned)xc < (unsigned)Wn);
            nv += ok;
            mk[t] = ok ? ~0ull : 0ull;
            nb[t] = ok ? bp[yy * Wn + xc] : 0ull;
        }
    float basef = 64.f * (float)nv;

    const float* rp = resid + (size_t)b * Cn * HW + hw;
    float*       op = outp  + (size_t)b * Cn * HW + hw;

    unsigned long long pk = 0ull;

    #pragma unroll 1
    for (int chunk = 0; chunk < 8; chunk++) {
        const int oc0 = chunk * 8;

        // Phase 1: batch independent residual loads (long-scoreboard, MLP=8)
        float r[8];
        #pragma unroll
        for (int j = 0; j < 8; j++)
            r[j] = rp[(oc0 + j) * HW];

        // Phase 2: pure-ALU popcount for 8 output channels
        int acc[8];
        #pragma unroll
        for (int j = 0; j < 8; j++) {
            const unsigned long long* wr = sw + (oc0 + j) * 9;
            int a = 0;
            #pragma unroll
            for (int t = 0; t < 9; t++)
                a += __popcll((nb[t] ^ wr[t]) & mk[t]);
            acc[j] = a;
        }

        // Phase 3: float epilogue + stores (loads have arrived by now)
        #pragma unroll
        for (int j = 0; j < 8; j++) {
            const int oc = oc0 + j;
            float conv = ss[oc] * fmaf(-2.f, (float)acc[j], basef);
            float o  = fmaf(ALPHA, conv, r[j]);
            float tm = o + sA[oc];
            o = (tm >= 0.f ? tm : sP[oc] * tm) + sB[oc];
            op[oc * HW] = o;
            if (STAGE == 1)
                pk |= (unsigned long long)(o + sK[oc] >= 0.f) << oc;
        }
    }
    if (STAGE == 1) g_bits2[pix] = pk;
}

__global__ void __launch_bounds__(256, 3)
conv1_kernel(const float* __restrict__ x,
             const float* __restrict__ b12,
             const float* __restrict__ a1,
             const float* __restrict__ b13,
             const float* __restrict__ b21)
{
    conv_body<1>(x, g_out1, b12, a1, b13, b21);
}

__global__ void __launch_bounds__(256, 3)
conv2_kernel(float* __restrict__ out,
             const float* __restrict__ b22,
             const float* __restrict__ a2,
             const float* __restrict__ b23)
{
    conv_body<2>(g_out1, out, b22, a2, b23, nullptr);
}

// ---------------------------------------------------------------------------
extern "C" void kernel_launch(void* const* d_in, const int* in_sizes, int n_in,
                              void* d_out, int out_size)
{
    const float* x   = (const float*)d_in[0];
    const float* w3  = (const float*)d_in[1];
    const float* wpw = (const float*)d_in[2];
    const float* b11 = (const float*)d_in[3];
    const float* b12 = (const float*)d_in[4];
    const float* b13 = (const float*)d_in[5];
    const float* b21 = (const float*)d_in[6];
    const float* b22 = (const float*)d_in[7];
    const float* b23 = (const float*)d_in[8];
    const float* a1  = (const float*)d_in[9];
    const float* a2  = (const float*)d_in[10];
    float* out = (float*)d_out;

    int blocks = (BHW + 255) / 256;
    prep_weights<<<1, 128>>>(w3, wpw);
    pack1_kernel<<<blocks, 256>>>(x, b11);
    conv1_kernel<<<blocks, 256>>>(x, b12, a1, b13, b21);
    conv2_kernel<<<blocks, 256>>>(out, b22, a2, b23);
}